// round 16
// baseline (speedup 1.0000x reference)
#include <cuda_runtime.h>

#define BB 32
#define SS 1024
#define DD 512
#define MAXL 8192   // durations in [1,8], S=1024 -> mel_len <= 8192

// 256-bit global load (L1-bypass/nc) and streaming store (sm_100+ PTX v8)
__device__ __forceinline__ void ldg256(const float* p, float* v) {
    asm volatile("ld.global.nc.v8.f32 {%0,%1,%2,%3,%4,%5,%6,%7}, [%8];"
                 : "=f"(v[0]), "=f"(v[1]), "=f"(v[2]), "=f"(v[3]),
                   "=f"(v[4]), "=f"(v[5]), "=f"(v[6]), "=f"(v[7])
                 : "l"(p));
}
__device__ __forceinline__ void stg256_cs(float* p, const float* v) {
    asm volatile("st.global.cs.v8.f32 [%0], {%1,%2,%3,%4,%5,%6,%7,%8};"
                 :: "l"(p),
                    "f"(v[0]), "f"(v[1]), "f"(v[2]), "f"(v[3]),
                    "f"(v[4]), "f"(v[5]), "f"(v[6]), "f"(v[7])
                 : "memory");
}

// warp-level 2-level 32-ary search over smem csum; requires t < mel.
// s1 = lvl1[lane] already in a register.
__device__ __forceinline__ int warp_search(const int* s, int s1,
                                           int t, int lane)
{
    const unsigned m1 = __ballot_sync(0xffffffff, s1 > t);
    const int seg = __ffs(m1) - 1;
    const int s2 = s[(seg << 5) + lane];
    const unsigned m2 = __ballot_sync(0xffffffff, s2 > t);
    return (seg << 5) + __ffs(m2) - 1;   // first i with csum[i] > t
}

// ---------------------------------------------------------------------------
// Single kernel, no inter-block sync. 256 threads = 8 warps; each block
// handles 16 output rows (2 per warp, INTERLEAVED schedule — measured best).
//  prologue: int4 warp-shuffle scan of durations[b] -> smem csum + lvl1
//  payload per row: 2-level ballot search, 2x LDG.256, 2x STG.256(.cs)
// ---------------------------------------------------------------------------
__global__ __launch_bounds__(256)
void lr_fused_kernel(const int*   __restrict__ dur,
                     const float* __restrict__ x,
                     float*       __restrict__ out,
                     float*       __restrict__ mel_len_out,
                     float*       __restrict__ mask_out,
                     int max_len, int has_tail)
{
    __shared__ int s[SS];      // inclusive csum of durations[b]
    __shared__ int lvl1[32];   // s[32j+31]
    __shared__ int wsum[8];

    const int b    = blockIdx.y;
    const int tid  = threadIdx.x;
    const int lane = tid & 31;
    const int wid  = tid >> 5;

    // ---- prologue: scan durations[b] into smem (int4/thread) ----
    const int4 d = __ldg(((const int4*)(dur + b * SS)) + tid);
    const int p0 = d.x;
    const int p1 = p0 + d.y;
    const int p2 = p1 + d.z;
    const int p3 = p2 + d.w;
    int tot = p3;
    #pragma unroll
    for (int off = 1; off < 32; off <<= 1) {
        int n = __shfl_up_sync(0xffffffff, tot, off);
        if (lane >= off) tot += n;
    }
    if (lane == 31) wsum[wid] = tot;
    __syncthreads();
    if (wid == 0 && lane < 8) {
        int w = wsum[lane];
        #pragma unroll
        for (int off = 1; off < 8; off <<= 1) {
            int n = __shfl_up_sync(0xff, w, off);
            if (lane >= off) w += n;
        }
        wsum[lane] = w;
    }
    __syncthreads();
    const int base = (tot - p3) + ((wid > 0) ? wsum[wid - 1] : 0);
    s[4 * tid + 0] = base + p0;
    s[4 * tid + 1] = base + p1;
    s[4 * tid + 2] = base + p2;
    s[4 * tid + 3] = base + p3;
    if ((tid & 7) == 7) lvl1[tid >> 3] = base + p3;   // element 32j+31
    __syncthreads();

    // ---- payload: TWO rows per warp, interleaved (R13 schedule) ----
    const int t0 = blockIdx.x * 16 + wid * 2;   // rows t0, t0+1
    if (t0 >= max_len) return;
    const int t1 = t0 + 1;
    const bool has1 = t1 < max_len;

    const int s1  = lvl1[lane];                       // one LDS per warp
    const int mel = __shfl_sync(0xffffffff, s1, 31);  // csum[S-1]
    const int bS  = b * SS;

    if (has_tail) {
        if (blockIdx.x == 0 && tid == 0) mel_len_out[b] = (float)mel;
        if (lane == 0) {
            const float m0 = (t0 >= mel) ? 1.0f : 0.0f;
            if (has1) {
                const float m1v = (t1 >= mel) ? 1.0f : 0.0f;
                float2 mm = make_float2(m0, m1v);     // one 64-bit store
                *(float2*)(mask_out + b * max_len + t0) = mm;
            } else {
                mask_out[b * max_len + t0] = m0;
            }
        }
    }

    const float z[8] = {0.f,0.f,0.f,0.f,0.f,0.f,0.f,0.f};
    float* ob0 = out + ((long)(b * max_len + t0)) * DD + lane * 8;

    // row 0
    if (t0 >= mel) {
        stg256_cs(ob0,       z);
        stg256_cs(ob0 + 256, z);
    } else {
        const int lo = warp_search(s, s1, t0, lane);
        const float* ib = x + ((long)(bS + lo)) * DD + lane * 8;
        float v0[8], v1[8];
        ldg256(ib,       v0);
        ldg256(ib + 256, v1);
        stg256_cs(ob0,       v0);
        stg256_cs(ob0 + 256, v1);
    }

    // row 1
    if (has1) {
        float* ob1 = ob0 + DD;
        if (t1 >= mel) {
            stg256_cs(ob1,       z);
            stg256_cs(ob1 + 256, z);
        } else {
            const int lo = warp_search(s, s1, t1, lane);
            const float* ib = x + ((long)(bS + lo)) * DD + lane * 8;
            float v0[8], v1[8];
            ldg256(ib,       v0);
            ldg256(ib + 256, v1);
            stg256_cs(ob1,       v0);
            stg256_cs(ob1 + 256, v1);
        }
    }
}

// ---------------------------------------------------------------------------
extern "C" void kernel_launch(void* const* d_in, const int* in_sizes, int n_in,
                              void* d_out, int out_size)
{
    const float* x   = (const float*)d_in[0];
    const int*   dur = (const int*)d_in[1];
    float*       out = (float*)d_out;

    // Recover max_len from out_size (tuple layout vs expanded-only).
    long L;
    int has_tail;
    long os = (long)out_size;
    if ((os - BB) > 0 && ((os - BB) % ((long)BB * (DD + 1))) == 0) {
        L = (os - BB) / ((long)BB * (DD + 1));
        has_tail = 1;
    } else {
        L = os / ((long)BB * DD);
        has_tail = 0;
    }
    if (L <= 0 || L > MAXL) return;

    const int max_len = (int)L;
    const int bpb = (max_len + 15) / 16;   // blocks per batch (16 rows/block)

    float* mel_len_out = out + (long)BB * max_len * DD;   // B floats
    float* mask_out    = mel_len_out + BB;                // B*L floats

    dim3 grid((unsigned)bpb, BB, 1);
    lr_fused_kernel<<<grid, 256>>>(dur, x, out, mel_len_out, mask_out,
                                   max_len, has_tail);
}

// round 17
// speedup vs baseline: 1.0052x; 1.0052x over previous
#include <cuda_runtime.h>

#define BB 32
#define SS 1024
#define DD 512
#define MAXL 8192   // durations in [1,8], S=1024 -> mel_len <= 8192

// 256-bit global load (L1-bypass/nc) and streaming store (sm_100+ PTX v8)
__device__ __forceinline__ void ldg256(const float* p, float* v) {
    asm volatile("ld.global.nc.v8.f32 {%0,%1,%2,%3,%4,%5,%6,%7}, [%8];"
                 : "=f"(v[0]), "=f"(v[1]), "=f"(v[2]), "=f"(v[3]),
                   "=f"(v[4]), "=f"(v[5]), "=f"(v[6]), "=f"(v[7])
                 : "l"(p));
}
__device__ __forceinline__ void stg256_cs(float* p, const float* v) {
    asm volatile("st.global.cs.v8.f32 [%0], {%1,%2,%3,%4,%5,%6,%7,%8};"
                 :: "l"(p),
                    "f"(v[0]), "f"(v[1]), "f"(v[2]), "f"(v[3]),
                    "f"(v[4]), "f"(v[5]), "f"(v[6]), "f"(v[7])
                 : "memory");
}

// warp-level 2-level 32-ary search over smem csum; requires t < mel.
// s1 = lvl1[lane] already in a register.
__device__ __forceinline__ int warp_search(const int* s, int s1,
                                           int t, int lane)
{
    const unsigned m1 = __ballot_sync(0xffffffff, s1 > t);
    const int seg = __ffs(m1) - 1;
    const int s2 = s[(seg << 5) + lane];
    const unsigned m2 = __ballot_sync(0xffffffff, s2 > t);
    return (seg << 5) + __ffs(m2) - 1;   // first i with csum[i] > t
}

// ---------------------------------------------------------------------------
// Single fused kernel (terminal structure, best measured: 58.3us).
// 256 threads = 8 warps; each block handles 16 output rows of one batch
// (2 rows per warp, interleaved schedule).
//  prologue: int4 warp-shuffle scan of durations[b] -> smem csum + lvl1
//  payload per row: 2-level ballot search, 2x LDG.256, 2x STG.256(.cs)
// The 311MB of output writes are compulsory; kernel runs at the DRAM write
// ceiling (~5.46 TB/s measured across 10 structural variants).
// ---------------------------------------------------------------------------
__global__ __launch_bounds__(256)
void lr_fused_kernel(const int*   __restrict__ dur,
                     const float* __restrict__ x,
                     float*       __restrict__ out,
                     float*       __restrict__ mel_len_out,
                     float*       __restrict__ mask_out,
                     int max_len, int bpb, int has_tail)
{
    __shared__ int s[SS];      // inclusive csum of durations[b]
    __shared__ int lvl1[32];   // s[32j+31]
    __shared__ int wsum[8];

    const int bid   = blockIdx.x;
    const int b     = bid / bpb;          // batch
    const int chunk = bid - b * bpb;      // 16-row chunk within batch
    const int tid   = threadIdx.x;
    const int lane  = tid & 31;
    const int wid   = tid >> 5;

    // ---- prologue: scan durations[b] into smem (int4/thread) ----
    const int4 d = __ldg(((const int4*)(dur + b * SS)) + tid);
    const int p0 = d.x;
    const int p1 = p0 + d.y;
    const int p2 = p1 + d.z;
    const int p3 = p2 + d.w;
    int tot = p3;
    #pragma unroll
    for (int off = 1; off < 32; off <<= 1) {
        int n = __shfl_up_sync(0xffffffff, tot, off);
        if (lane >= off) tot += n;
    }
    if (lane == 31) wsum[wid] = tot;
    __syncthreads();
    if (wid == 0 && lane < 8) {
        int w = wsum[lane];
        #pragma unroll
        for (int off = 1; off < 8; off <<= 1) {
            int n = __shfl_up_sync(0xff, w, off);
            if (lane >= off) w += n;
        }
        wsum[lane] = w;
    }
    __syncthreads();
    const int base = (tot - p3) + ((wid > 0) ? wsum[wid - 1] : 0);
    s[4 * tid + 0] = base + p0;
    s[4 * tid + 1] = base + p1;
    s[4 * tid + 2] = base + p2;
    s[4 * tid + 3] = base + p3;
    if ((tid & 7) == 7) lvl1[tid >> 3] = base + p3;   // element 32j+31
    __syncthreads();

    // ---- payload: TWO rows per warp, interleaved ----
    const int t0 = chunk * 16 + wid * 2;   // rows t0, t0+1
    if (t0 >= max_len) return;
    const int t1 = t0 + 1;
    const bool has1 = t1 < max_len;

    const int s1  = lvl1[lane];                       // one LDS per warp
    const int mel = __shfl_sync(0xffffffff, s1, 31);  // csum[S-1]
    const int bS  = b * SS;

    if (has_tail) {
        if (chunk == 0 && tid == 0) mel_len_out[b] = (float)mel;
        if (lane == 0) {
            const float m0 = (t0 >= mel) ? 1.0f : 0.0f;
            if (has1) {
                const float m1v = (t1 >= mel) ? 1.0f : 0.0f;
                *(float2*)(mask_out + b * max_len + t0) = make_float2(m0, m1v);
            } else {
                mask_out[b * max_len + t0] = m0;
            }
        }
    }

    const float z[8] = {0.f,0.f,0.f,0.f,0.f,0.f,0.f,0.f};
    float* ob0 = out + ((long)(b * max_len + t0)) * DD + lane * 8;

    // row 0
    if (t0 >= mel) {
        stg256_cs(ob0,       z);
        stg256_cs(ob0 + 256, z);
    } else {
        const int lo = warp_search(s, s1, t0, lane);
        const float* ib = x + ((long)(bS + lo)) * DD + lane * 8;
        float v0[8], v1[8];
        ldg256(ib,       v0);
        ldg256(ib + 256, v1);
        stg256_cs(ob0,       v0);
        stg256_cs(ob0 + 256, v1);
    }

    // row 1
    if (has1) {
        float* ob1 = ob0 + DD;
        if (t1 >= mel) {
            stg256_cs(ob1,       z);
            stg256_cs(ob1 + 256, z);
        } else {
            const int lo = warp_search(s, s1, t1, lane);
            const float* ib = x + ((long)(bS + lo)) * DD + lane * 8;
            float v0[8], v1[8];
            ldg256(ib,       v0);
            ldg256(ib + 256, v1);
            stg256_cs(ob1,       v0);
            stg256_cs(ob1 + 256, v1);
        }
    }
}

// ---------------------------------------------------------------------------
extern "C" void kernel_launch(void* const* d_in, const int* in_sizes, int n_in,
                              void* d_out, int out_size)
{
    const float* x   = (const float*)d_in[0];
    const int*   dur = (const int*)d_in[1];
    float*       out = (float*)d_out;

    // Recover max_len from out_size (tuple layout vs expanded-only).
    long L;
    int has_tail;
    long os = (long)out_size;
    if ((os - BB) > 0 && ((os - BB) % ((long)BB * (DD + 1))) == 0) {
        L = (os - BB) / ((long)BB * (DD + 1));
        has_tail = 1;
    } else {
        L = os / ((long)BB * DD);
        has_tail = 0;
    }
    if (L <= 0 || L > MAXL) return;

    const int max_len = (int)L;
    const int bpb = (max_len + 15) / 16;   // 16-row chunks per batch

    float* mel_len_out = out + (long)BB * max_len * DD;   // B floats
    float* mask_out    = mel_len_out + BB;                // B*L floats

    lr_fused_kernel<<<BB * bpb, 256>>>(dur, x, out, mel_len_out, mask_out,
                                       max_len, bpb, has_tail);
}